// round 1
// baseline (speedup 1.0000x reference)
#include <cuda_runtime.h>
#include <cuda_bf16.h>

// Problem constants (fixed by setup_inputs)
#define B_   16
#define N_   1024
#define G_   64
#define BN_  (B_ * N_)          // 16384 anchors
#define C_   8                  // NUM_CLASSES
#define FW_  16
#define FH_  16
#define SP_  (FW_ * FH_)        // 256 spatial cells

// Output layout: concat of flattened [label_map (BN,8,16,16)] [offset (BN,4,16,16)] [mask (BN,8)]
#define LM_TOTAL  ((size_t)BN_ * C_ * SP_)     // 16384*2048
#define OFF_TOTAL ((size_t)BN_ * 4 * SP_)      // 16384*1024

__global__ __launch_bounds__(SP_) void rcnn_label_kernel(
    const float* __restrict__ boxes,       // (BN,4)
    const float* __restrict__ gt_boxes,    // (B,G,5)
    const int*   __restrict__ match_flag,  // (BN)
    const int*   __restrict__ match_gid,   // (BN)
    float*       __restrict__ out)
{
    const int a = blockIdx.x;      // anchor index in [0, BN)
    const int t = threadIdx.x;     // spatial cell: ih*16+iw

    // ---- per-anchor scalars (broadcast loads) ----
    const float4 bx = __ldg(reinterpret_cast<const float4*>(boxes) + a);
    const int b   = a >> 10;                       // a / N_
    const int gid = __ldg(match_gid + a);
    const float* gt = gt_boxes + (size_t)(b * G_ + gid) * 5;
    const float g0 = __ldg(gt + 0);
    const float g1 = __ldg(gt + 1);
    const float g2 = __ldg(gt + 2);
    const float g3 = __ldg(gt + 3);
    const float box_label = __ldg(gt + 4);

    // zoom boxes about center (ZOOM=1.1 -> half-extent scale 0.55)
    const float cx = (bx.x + bx.z) * 0.5f;
    const float cy = (bx.y + bx.w) * 0.5f;
    const float hw = (bx.z - bx.x) * 0.55f;
    const float hh = (bx.w - bx.y) * 0.55f;
    const float ax1 = cx - hw, ay1 = cy - hh;
    const float ax2 = cx + hw, ay2 = cy + hh;

    const float rx1 = g0 - ax1, ry1 = g1 - ay1;
    const float rx2 = g2 - ax1, ry2 = g3 - ay1;
    const float rw = rx2 - rx1, rh = ry2 - ry1;
    const float rcx = (rx1 + rx2) * 0.5f;
    const float rcy = (ry1 + ry2) * 0.5f;
    const float sw = (ax2 - ax1) * (1.0f / (float)FW_);   // exact: /16
    const float sh = (ay2 - ay1) * (1.0f / (float)FH_);

    const float inv_sw = 1.0f / sw;
    const float inv_sh = 1.0f / sh;
    const float sig_w = rw * 0.5f * inv_sw;
    const float sig_h = rh * 0.5f * inv_sh;
    const float pw = rcx * inv_sw;
    const float ph = rcy * inv_sh;

    const bool small = (sw < 0.01f) | (sh < 0.01f);

    // ---- per spatial-cell values ----
    const float fiw = (float)(t & 15) + 0.5f;
    const float fih = (float)(t >> 4) + 0.5f;

    const float ddx = pw - fiw;
    const float ddy = ph - fih;
    const bool cond = (fabsf(ddx) < sig_w) & (fabsf(ddy) < sig_h);
    float gval = 0.0f;
    if (cond & !small) {
        const float dx = ddx / sig_w;
        const float dy = ddy / sig_h;
        gval = expf(-(dx * dx + dy * dy));
    }

    const float clsf = fabsf(box_label) - 1.0f;

    // label_map: 8 coalesced plane writes
    float* lm = out + (size_t)a * (C_ * SP_);
#pragma unroll
    for (int c = 0; c < C_; ++c) {
        lm[c * SP_ + t] = ((float)c == clsf) ? gval : 0.0f;
    }

    // offset: 4 coalesced plane writes
    float o0 = rx1 * inv_sw - fiw;
    float o1 = ry1 * inv_sh - fih;
    float o2 = rx2 * inv_sw - fiw;
    float o3 = ry2 * inv_sh - fih;
    if (small) { o0 = o1 = o2 = o3 = 0.0f; }
    float* off = out + LM_TOTAL + (size_t)a * (4 * SP_);
    off[0 * SP_ + t] = o0;
    off[1 * SP_ + t] = o1;
    off[2 * SP_ + t] = o2;
    off[3 * SP_ + t] = o3;

    // mask: 8 values per anchor (bool -> 1.0/0.0 float)
    if (t < C_) {
        const int fl = __ldg(match_flag + a);
        const bool pos = fl > 0;
        const float non_neg = (fl != 0) ? box_label : 0.0f;
        const bool m1 = pos & (non_neg > 0.0f);
        const bool mv = m1 & ((float)t == clsf);
        out[LM_TOTAL + OFF_TOTAL + (size_t)a * C_ + t] = mv ? 1.0f : 0.0f;
    }
}

extern "C" void kernel_launch(void* const* d_in, const int* in_sizes, int n_in,
                              void* d_out, int out_size) {
    const float* boxes    = (const float*)d_in[0];
    const float* gt_boxes = (const float*)d_in[1];
    const int*   flag     = (const int*)d_in[2];
    const int*   gid      = (const int*)d_in[3];
    float* out = (float*)d_out;

    rcnn_label_kernel<<<BN_, SP_>>>(boxes, gt_boxes, flag, gid, out);
}

// round 3
// speedup vs baseline: 1.1801x; 1.1801x over previous
#include <cuda_runtime.h>
#include <cuda_bf16.h>

// Problem constants (fixed by setup_inputs)
#define B_   16
#define N_   1024
#define G_   64
#define BN_  (B_ * N_)          // 16384 anchors
#define C_   8                  // NUM_CLASSES
#define FW_  16
#define FH_  16
#define SP_  (FW_ * FH_)        // 256 spatial cells
#define ANCHORS_PER_CTA 4
#define THREADS_PER_ANCHOR 64   // each thread owns 4 consecutive cells (float4)

// Output layout: concat of [label_map (BN,8,16,16)] [offset (BN,4,16,16)] [mask (BN,8)]
#define LM_TOTAL  ((size_t)BN_ * C_ * SP_)
#define OFF_TOTAL ((size_t)BN_ * 4 * SP_)

__global__ __launch_bounds__(ANCHORS_PER_CTA * THREADS_PER_ANCHOR)
void rcnn_label_kernel(
    const float* __restrict__ boxes,       // (BN,4)
    const float* __restrict__ gt_boxes,    // (B,G,5)
    const int*   __restrict__ match_flag,  // (BN)
    const int*   __restrict__ match_gid,   // (BN)
    float*       __restrict__ out)
{
    const int t  = threadIdx.x & (THREADS_PER_ANCHOR - 1);  // 0..63 within anchor
    const int la = threadIdx.x >> 6;                        // local anchor 0..3
    const int a  = blockIdx.x * ANCHORS_PER_CTA + la;

    // ---- per-anchor scalars (broadcast loads within the 2-warp group) ----
    const float4 bx = __ldg(reinterpret_cast<const float4*>(boxes) + a);
    const int b   = a >> 10;                       // a / N_
    const int gid = __ldg(match_gid + a);
    const float* gt = gt_boxes + (size_t)(b * G_ + gid) * 5;
    const float g0 = __ldg(gt + 0);
    const float g1 = __ldg(gt + 1);
    const float g2 = __ldg(gt + 2);
    const float g3 = __ldg(gt + 3);
    const float box_label = __ldg(gt + 4);

    // zoom boxes about center (ZOOM=1.1 -> half-extent scale 0.55)
    const float cx = (bx.x + bx.z) * 0.5f;
    const float cy = (bx.y + bx.w) * 0.5f;
    const float hw = (bx.z - bx.x) * 0.55f;
    const float hh = (bx.w - bx.y) * 0.55f;
    const float ax1 = cx - hw, ay1 = cy - hh;
    const float ax2 = cx + hw, ay2 = cy + hh;

    const float rx1 = g0 - ax1, ry1 = g1 - ay1;
    const float rx2 = g2 - ax1, ry2 = g3 - ay1;
    const float rw = rx2 - rx1, rh = ry2 - ry1;
    const float rcx = (rx1 + rx2) * 0.5f;
    const float rcy = (ry1 + ry2) * 0.5f;
    const float sw = (ax2 - ax1) * (1.0f / (float)FW_);
    const float sh = (ay2 - ay1) * (1.0f / (float)FH_);

    const float inv_sw = 1.0f / sw;
    const float inv_sh = 1.0f / sh;
    const float sig_w = rw * 0.5f * inv_sw;
    const float sig_h = rh * 0.5f * inv_sh;
    const float inv_sig_w = 1.0f / sig_w;
    const float inv_sig_h = 1.0f / sig_h;
    const float pw = rcx * inv_sw;
    const float ph = rcy * inv_sh;

    const bool small = (sw < 0.01f) | (sh < 0.01f);

    // ---- 4 consecutive spatial cells: base cell = 4*t (iw fastest, 4|16) ----
    const int cell = t << 2;
    const float fiw0 = (float)(cell & 15) + 0.5f;
    const float fih  = (float)(cell >> 4) + 0.5f;

    const float ddy   = ph - fih;
    const bool  condy = (fabsf(ddy) < sig_h) & !small;
    const float dy    = ddy * inv_sig_h;
    const float ey    = dy * dy;

    float4 g4;
    {
        float gv[4];
#pragma unroll
        for (int j = 0; j < 4; ++j) {
            const float ddx = pw - (fiw0 + (float)j);
            float v = 0.0f;
            if (condy & (fabsf(ddx) < sig_w)) {
                const float dx = ddx * inv_sig_w;
                v = __expf(-(dx * dx + ey));
            }
            gv[j] = v;
        }
        g4 = make_float4(gv[0], gv[1], gv[2], gv[3]);
    }
    const float4 z4 = make_float4(0.f, 0.f, 0.f, 0.f);

    const float clsf = fabsf(box_label) - 1.0f;

    // label_map: 8 plane writes, float4 each (warp covers 512B contiguous)
    float4* lm = reinterpret_cast<float4*>(out + (size_t)a * (C_ * SP_)) + t;
#pragma unroll
    for (int c = 0; c < C_; ++c) {
        lm[c * (SP_ / 4)] = ((float)c == clsf) ? g4 : z4;
    }

    // offset: 4 plane writes, float4 each
    const float bx1 = rx1 * inv_sw - fiw0;   // decreases by 1 per j
    const float bx2 = rx2 * inv_sw - fiw0;
    const float oy1 = small ? 0.f : (ry1 * inv_sh - fih);
    const float oy2 = small ? 0.f : (ry2 * inv_sh - fih);

    float4 o0, o2;
    if (small) {
        o0 = z4; o2 = z4;
    } else {
        o0 = make_float4(bx1, bx1 - 1.f, bx1 - 2.f, bx1 - 3.f);
        o2 = make_float4(bx2, bx2 - 1.f, bx2 - 2.f, bx2 - 3.f);
    }
    const float4 o1 = make_float4(oy1, oy1, oy1, oy1);
    const float4 o3 = make_float4(oy2, oy2, oy2, oy2);

    float4* off = reinterpret_cast<float4*>(out + LM_TOTAL + (size_t)a * (4 * SP_)) + t;
    off[0 * (SP_ / 4)] = o0;
    off[1 * (SP_ / 4)] = o1;
    off[2 * (SP_ / 4)] = o2;
    off[3 * (SP_ / 4)] = o3;

    // mask: 8 values per anchor
    if (t < C_) {
        const int fl = __ldg(match_flag + a);
        const bool pos = fl > 0;
        const float non_neg = (fl != 0) ? box_label : 0.0f;
        const bool m1 = pos & (non_neg > 0.0f);
        const bool mv = m1 & ((float)t == clsf);
        out[LM_TOTAL + OFF_TOTAL + (size_t)a * C_ + t] = mv ? 1.0f : 0.0f;
    }
}

extern "C" void kernel_launch(void* const* d_in, const int* in_sizes, int n_in,
                              void* d_out, int out_size) {
    const float* boxes    = (const float*)d_in[0];
    const float* gt_boxes = (const float*)d_in[1];
    const int*   flag     = (const int*)d_in[2];
    const int*   gid      = (const int*)d_in[3];
    float* out = (float*)d_out;

    rcnn_label_kernel<<<BN_ / ANCHORS_PER_CTA, ANCHORS_PER_CTA * THREADS_PER_ANCHOR>>>(
        boxes, gt_boxes, flag, gid, out);
}